// round 14
// baseline (speedup 1.0000x reference)
#include <cuda_runtime.h>
#include <cuda.h>
#include <cuda_fp16.h>
#include <cstring>

#define ACTIVE     32
#define HIDDEN     256
#define ACCDIM     512
#define NTHREADS   256
#define NWARPS     (NTHREADS / 32)
#define INPUTSZ    40960
#define ROWB       512                          // bytes per fp16 row
#define CHUNKB     (4 * ROWB)                   // gather4 payload = 2 KB

__device__ __forceinline__ unsigned int h2_to_u32(__half2 h) {
    return *reinterpret_cast<unsigned int*>(&h);
}
__device__ __forceinline__ __half2 u32_to_h2(unsigned int u) {
    return *reinterpret_cast<__half2*>(&u);
}
__device__ __forceinline__ float satf(float x) { return __saturatef(x); }

__device__ __forceinline__ void fma_f32x2(unsigned long long& d,
                                          unsigned long long a,
                                          unsigned long long b) {
    asm("fma.rn.f32x2 %0, %1, %2, %0;" : "+l"(d) : "l"(a), "l"(b));
}
__device__ __forceinline__ unsigned long long pack_f32x2(float lo, float hi) {
    unsigned long long v;
    asm("mov.b64 %0, {%1, %2};" : "=l"(v)
        : "r"(__float_as_uint(lo)), "r"(__float_as_uint(hi)));
    return v;
}
__device__ __forceinline__ float f32x2_hsum(unsigned long long v) {
    unsigned int lo, hi;
    asm("mov.b64 {%0,%1}, %2;" : "=r"(lo), "=r"(hi) : "l"(v));
    return __uint_as_float(lo) + __uint_as_float(hi);
}

__device__ __forceinline__ unsigned int smem_u32(const void* p) {
    unsigned int a;
    asm("{ .reg .u64 t; cvta.to.shared.u64 t, %1; cvt.u32.u64 %0, t; }"
        : "=r"(a) : "l"(p));
    return a;
}

__device__ __forceinline__ void mbar_init(unsigned int mbar, unsigned int cnt) {
    asm volatile("mbarrier.init.shared.b64 [%0], %1;" :: "r"(mbar), "r"(cnt) : "memory");
}
__device__ __forceinline__ void mbar_expect_tx(unsigned int mbar, unsigned int bytes) {
    asm volatile("mbarrier.arrive.expect_tx.shared.b64 _, [%0], %1;"
                 :: "r"(mbar), "r"(bytes) : "memory");
}
__device__ __forceinline__ void mbar_wait(unsigned int mbar, unsigned int parity) {
    asm volatile(
        "{\n\t.reg .pred P;\n"
        "W_%=:\n\t"
        "mbarrier.try_wait.parity.acquire.cta.shared::cta.b64 P, [%0], %1;\n\t"
        "@P bra.uni D_%=;\n\t"
        "bra.uni W_%=;\n"
        "D_%=:\n\t}"
        :: "r"(mbar), "r"(parity) : "memory");
}
__device__ __forceinline__ void fence_proxy_async_cta() {
    asm volatile("fence.proxy.async.shared::cta;" ::: "memory");
}
// TMA gather4 (sm_100a: CTA-scoped shared destination)
__device__ __forceinline__ void tma_gather4(unsigned int dst, const CUtensorMap* m,
                                            int x, int r0, int r1, int r2, int r3,
                                            unsigned int mbar) {
    asm volatile(
        "cp.async.bulk.tensor.2d.tile::gather4.shared::cta.global.mbarrier::complete_tx::bytes "
        "[%0], [%1, {%2, %3, %4, %5, %6}], [%7];"
        :: "r"(dst), "l"(m), "r"(x), "r"(r0), "r"(r1), "r"(r2), "r"(r3), "r"(mbar)
        : "memory");
}

// fp16 shadow of ft_w: 40960 rows x 256 halves = 512B/row
__device__ uint4 g_ftw_h[INPUTSZ * 32];
// l1_w transposed+packed fp16: [j4][k] -> 4 halves as uint2
__device__ uint2 g_l1w_h[128 * 32];

// dynamic smem layout (bytes):
//   [0, 32K)      sh_stg : NWARPS * 2 bufs * 2KB  black-side staging
//   [32K, +128)   sh_mbar: NWARPS * 2 mbarriers
//   sh_w1h (32KB fp16 weights), sh_l2t (4KB), sh_acc (32KB)
#define OFF_STG    0
#define OFF_MBAR   (NWARPS * 2 * CHUNKB)
#define OFF_W1H    (OFF_MBAR + 128)
#define OFF_L2T    (OFF_W1H + 128 * 32 * 8)
#define OFF_ACC    (OFF_L2T + 32 * 32 * 4)
#define SMEM_BYTES (OFF_ACC + NWARPS * 2 * ACCDIM * 4)

// ---------- merged prepass (one launch; every call; deterministic) ----------
__global__ void prepass_kernel(const float* __restrict__ ft_w,
                               const float* __restrict__ l1_w, int n_u4)
{
    int i = blockIdx.x * blockDim.x + threadIdx.x;
    if (i < n_u4) {
        const float4* src = (const float4*)ft_w;
        float4 a = src[2 * i];
        float4 b = src[2 * i + 1];
        uint4 o;
        o.x = h2_to_u32(__floats2half2_rn(a.x, a.y));
        o.y = h2_to_u32(__floats2half2_rn(a.z, a.w));
        o.z = h2_to_u32(__floats2half2_rn(b.x, b.y));
        o.w = h2_to_u32(__floats2half2_rn(b.z, b.w));
        g_ftw_h[i] = o;
    }
    if (blockIdx.x == 0) {
        for (int t = threadIdx.x; t < 128 * 32; t += NTHREADS) {
            int j4 = t >> 5, k = t & 31;
            const float* r = l1_w + k * ACCDIM + j4 * 4;
            uint2 o;
            o.x = h2_to_u32(__floats2half2_rn(r[0], r[1]));
            o.y = h2_to_u32(__floats2half2_rn(r[2], r[3]));
            g_l1w_h[t] = o;
        }
    }
}

// ---------- shared tail: L1 GEMV (fp16 weights) + L2 + L3 ----------
__device__ __forceinline__ void network_tail(
    const uint2* sh_w1h, const float* sh_l2t,
    const ulonglong2* acc0_u2, const ulonglong2* acc1_u2,
    float l1b, float l2b, float l3w, float l3b,
    int lane, int p0, int p1, float* out)
{
    unsigned long long q00 = 0ull, q01 = 0ull;
    unsigned long long q10 = 0ull, q11 = 0ull;
    #pragma unroll 4
    for (int j4 = 0; j4 < 128; j4++) {
        const uint2 wp = sh_w1h[j4 * 32 + lane];
        const float2 wlo = __half22float2(u32_to_h2(wp.x));
        const float2 whi = __half22float2(u32_to_h2(wp.y));
        const unsigned long long W0 = pack_f32x2(wlo.x, wlo.y);
        const unsigned long long W1 = pack_f32x2(whi.x, whi.y);
        const ulonglong2 A0 = acc0_u2[j4];
        const ulonglong2 A1 = acc1_u2[j4];
        fma_f32x2(q00, A0.x, W0); fma_f32x2(q01, A0.y, W1);
        fma_f32x2(q10, A1.x, W0); fma_f32x2(q11, A1.y, W1);
    }
    const float x1_0 = satf(f32x2_hsum(q00) + f32x2_hsum(q01) + l1b);
    const float x1_1 = satf(f32x2_hsum(q10) + f32x2_hsum(q11) + l1b);
    __syncwarp();

    #pragma unroll
    for (int pp = 0; pp < 2; pp++) {
        const float x1 = pp ? x1_1 : x1_0;
        float s2 = l2b;
        #pragma unroll
        for (int j = 0; j < 32; j++) {
            const float xj = __shfl_sync(0xffffffffu, x1, j);
            s2 += xj * sh_l2t[j * 32 + lane];
        }
        const float x2 = satf(s2);
        float p = x2 * l3w;
        #pragma unroll
        for (int off = 16; off > 0; off >>= 1)
            p += __shfl_xor_sync(0xffffffffu, p, off);
        if (lane == 0)
            out[pp ? p1 : p0] = p + l3b;
    }
}

// ---------- main hybrid kernel: white via LDG, black via TMA gather4 ----------
__global__ __launch_bounds__(NTHREADS, 2)
void nnue_hybrid_kernel(
    const int*   __restrict__ white_idx,
    const int*   __restrict__ black_idx,
    const float* __restrict__ stm,
    const float* __restrict__ ft_b,
    const float* __restrict__ l2_w,
    const float* __restrict__ l1_b,
    const float* __restrict__ l2_b,
    const float* __restrict__ l3_w,
    const float* __restrict__ l3_b,
    float*       __restrict__ out,
    const __grid_constant__ CUtensorMap tmap,
    int B)
{
    extern __shared__ char smraw[];
    uint2* sh_w1h = (uint2*)(smraw + OFF_W1H);
    float* sh_l2t = (float*)(smraw + OFF_L2T);
    float* sh_acc = (float*)(smraw + OFF_ACC);

    const int tid = threadIdx.x;
    const int lane  = tid & 31;
    const int warp  = tid >> 5;

    for (int i = tid; i < 128 * 32; i += NTHREADS)
        sh_w1h[i] = g_l1w_h[i];
    for (int i = tid; i < 32 * 32; i += NTHREADS) {
        int j = i >> 5, k = i & 31;
        sh_l2t[i] = l2_w[k * 32 + j];
    }

    const unsigned int stg0 = smem_u32(smraw + OFF_STG + warp * 2 * CHUNKB);
    const unsigned int mbar0 = smem_u32(smraw + OFF_MBAR + warp * 16);
    if (lane == 0) {
        mbar_init(mbar0, 1);
        mbar_init(mbar0 + 8, 1);
    }
    __syncthreads();

    const int gwarp = blockIdx.x * NWARPS + warp;
    const int wstride = gridDim.x * NWARPS;

    float4* acc0_4 = (float4*)(sh_acc + warp * 2 * ACCDIM);
    float4* acc1_4 = acc0_4 + (ACCDIM / 4);
    const ulonglong2* acc0_u2 = (const ulonglong2*)acc0_4;
    const ulonglong2* acc1_u2 = (const ulonglong2*)acc1_4;

    const float l1b = l1_b[lane];
    const float l2b = l2_b[lane];
    const float l3w = l3_w[lane];
    const float l3b = l3_b[0];
    const float4* ftb4 = (const float4*)ft_b;
    const float4 fbA = ftb4[2 * lane];
    const float4 fbB = ftb4[2 * lane + 1];
    const __half2 hz = u32_to_h2(0u);

    unsigned int ph0 = 0, ph1 = 0;      // mbarrier phase per buffer
    const int G = B >> 1;

    for (int g = gwarp; g < G; g += wstride) {
        const int p0 = g * 2;
        const int p1 = p0 + 1;

        #pragma unroll
        for (int pp = 0; pp < 2; pp++) {
            const int pos = pp ? p1 : p0;
            float4* accp = pp ? acc1_4 : acc0_4;

            const int wi = white_idx[pos * ACTIVE + lane];     // per-lane white idx
            const int* bip = black_idx + pos * ACTIVE;         // lane0 reads for TMA

            float tw[8] = {0,0,0,0,0,0,0,0};
            float tb[8] = {0,0,0,0,0,0,0,0};

            // black prologue: order prior reads before async writes; issue
            // chunks 0 and 1 into the two buffers
            __syncwarp();
            fence_proxy_async_cta();
            if (lane == 0) {
                #pragma unroll
                for (int c = 0; c < 2; c++) {
                    mbar_expect_tx(mbar0 + 8 * c, CHUNKB);
                    tma_gather4(stg0 + c * CHUNKB, &tmap, 0,
                                __ldg(bip + 4*c), __ldg(bip + 4*c + 1),
                                __ldg(bip + 4*c + 2), __ldg(bip + 4*c + 3),
                                mbar0 + 8 * c);
                }
            }

            #pragma unroll 1
            for (int c = 0; c < 8; c++) {
                // ---- white chunk c: 4 rows via per-lane LDG.128 + HADD2 ----
                {
                    __half2 s0=hz, s1=hz, s2=hz, s3=hz;
                    #pragma unroll
                    for (int u = 0; u < 4; u++) {
                        const int j = c * 4 + u;
                        const int iw = __shfl_sync(0xffffffffu, wi, j);
                        const uint4 rw = __ldg(&g_ftw_h[(long)iw * 32 + lane]);
                        s0 = __hadd2(s0, u32_to_h2(rw.x));
                        s1 = __hadd2(s1, u32_to_h2(rw.y));
                        s2 = __hadd2(s2, u32_to_h2(rw.z));
                        s3 = __hadd2(s3, u32_to_h2(rw.w));
                    }
                    const float2 f0 = __half22float2(s0);
                    const float2 f1 = __half22float2(s1);
                    const float2 f2 = __half22float2(s2);
                    const float2 f3 = __half22float2(s3);
                    tw[0] += f0.x; tw[1] += f0.y; tw[2] += f1.x; tw[3] += f1.y;
                    tw[4] += f2.x; tw[5] += f2.y; tw[6] += f3.x; tw[7] += f3.y;
                }

                // ---- black chunk c: wait TMA buffer, sum via LDS, refill ----
                {
                    const int buf = c & 1;
                    if (buf == 0) { mbar_wait(mbar0, ph0); ph0 ^= 1; }
                    else          { mbar_wait(mbar0 + 8, ph1); ph1 ^= 1; }

                    const unsigned int src = stg0 + buf * CHUNKB + lane * 16;
                    __half2 s0=hz, s1=hz, s2=hz, s3=hz;
                    #pragma unroll
                    for (int u = 0; u < 4; u++) {
                        unsigned int r0, r1, r2, r3;
                        asm volatile("ld.shared.v4.u32 {%0,%1,%2,%3}, [%4];"
                                     : "=r"(r0), "=r"(r1), "=r"(r2), "=r"(r3)
                                     : "r"(src + u * ROWB));
                        s0 = __hadd2(s0, u32_to_h2(r0));
                        s1 = __hadd2(s1, u32_to_h2(r1));
                        s2 = __hadd2(s2, u32_to_h2(r2));
                        s3 = __hadd2(s3, u32_to_h2(r3));
                    }
                    const float2 f0 = __half22float2(s0);
                    const float2 f1 = __half22float2(s1);
                    const float2 f2 = __half22float2(s2);
                    const float2 f3 = __half22float2(s3);
                    tb[0] += f0.x; tb[1] += f0.y; tb[2] += f1.x; tb[3] += f1.y;
                    tb[4] += f2.x; tb[5] += f2.y; tb[6] += f3.x; tb[7] += f3.y;

                    if (c < 6) {
                        __syncwarp();
                        fence_proxy_async_cta();
                        if (lane == 0) {
                            const int cn = c + 2;
                            mbar_expect_tx(mbar0 + 8 * buf, CHUNKB);
                            tma_gather4(stg0 + buf * CHUNKB, &tmap, 0,
                                        __ldg(bip + 4*cn), __ldg(bip + 4*cn + 1),
                                        __ldg(bip + 4*cn + 2), __ldg(bip + 4*cn + 3),
                                        mbar0 + 8 * buf);
                        }
                    }
                }
            }

            // ---- clip + select + store acc ----
            float4 cw0 = make_float4(satf(tw[0]+fbA.x), satf(tw[1]+fbA.y),
                                     satf(tw[2]+fbA.z), satf(tw[3]+fbA.w));
            float4 cw1 = make_float4(satf(tw[4]+fbB.x), satf(tw[5]+fbB.y),
                                     satf(tw[6]+fbB.z), satf(tw[7]+fbB.w));
            float4 cb0 = make_float4(satf(tb[0]+fbA.x), satf(tb[1]+fbA.y),
                                     satf(tb[2]+fbA.z), satf(tb[3]+fbA.w));
            float4 cb1 = make_float4(satf(tb[4]+fbB.x), satf(tb[5]+fbB.y),
                                     satf(tb[6]+fbB.z), satf(tb[7]+fbB.w));

            const float s = stm[pos];
            const bool wfirst = (s > 0.5f);
            accp[2*lane]          = wfirst ? cw0 : cb0;
            accp[2*lane + 1]      = wfirst ? cw1 : cb1;
            accp[64 + 2*lane]     = wfirst ? cb0 : cw0;
            accp[64 + 2*lane + 1] = wfirst ? cb1 : cw1;
        }
        __syncwarp();

        network_tail(sh_w1h, sh_l2t, acc0_u2, acc1_u2,
                     l1b, l2b, l3w, l3b, lane, p0, p1, out);
    }
}

// ---------- fallback kernel (pure-LDG champion path) ----------
__global__ __launch_bounds__(NTHREADS, 2)
void nnue_fallback_kernel(
    const int*   __restrict__ white_idx,
    const int*   __restrict__ black_idx,
    const float* __restrict__ stm,
    const float* __restrict__ ft_b,
    const float* __restrict__ l2_w,
    const float* __restrict__ l1_b,
    const float* __restrict__ l2_b,
    const float* __restrict__ l3_w,
    const float* __restrict__ l3_b,
    float*       __restrict__ out,
    int B)
{
    extern __shared__ char smraw[];
    uint2* sh_w1h = (uint2*)(smraw + OFF_W1H);
    float* sh_l2t = (float*)(smraw + OFF_L2T);
    float* sh_acc = (float*)(smraw + OFF_ACC);

    const int tid = threadIdx.x;
    for (int i = tid; i < 128 * 32; i += NTHREADS)
        sh_w1h[i] = g_l1w_h[i];
    for (int i = tid; i < 32 * 32; i += NTHREADS) {
        int j = i >> 5, k = i & 31;
        sh_l2t[i] = l2_w[k * 32 + j];
    }
    __syncthreads();

    const int lane  = tid & 31;
    const int warp  = tid >> 5;
    const int gwarp = blockIdx.x * NWARPS + warp;
    const int wstride = gridDim.x * NWARPS;

    float4* acc0_4 = (float4*)(sh_acc + warp * 2 * ACCDIM);
    float4* acc1_4 = acc0_4 + (ACCDIM / 4);
    const ulonglong2* acc0_u2 = (const ulonglong2*)acc0_4;
    const ulonglong2* acc1_u2 = (const ulonglong2*)acc1_4;

    const float l1b = l1_b[lane];
    const float l2b = l2_b[lane];
    const float l3w = l3_w[lane];
    const float l3b = l3_b[0];
    const float4* ftb4 = (const float4*)ft_b;
    const float4 fbA = ftb4[2 * lane];
    const float4 fbB = ftb4[2 * lane + 1];

    const int G = B >> 1;

    for (int g = gwarp; g < G; g += wstride) {
        const int p0 = g * 2;
        const int p1 = p0 + 1;

        #pragma unroll
        for (int pp = 0; pp < 2; pp++) {
            const int pos = pp ? p1 : p0;
            float4* accp = pp ? acc1_4 : acc0_4;
            const int wi = white_idx[pos * ACTIVE + lane];
            const int bi = black_idx[pos * ACTIVE + lane];

            float w[8] = {0,0,0,0,0,0,0,0};
            float b[8] = {0,0,0,0,0,0,0,0};
            const __half2 hz = u32_to_h2(0u);

            #pragma unroll
            for (int c = 0; c < 8; c++) {
                __half2 sw0=hz, sw1=hz, sw2=hz, sw3=hz;
                __half2 sb0=hz, sb1=hz, sb2=hz, sb3=hz;
                #pragma unroll
                for (int u = 0; u < 4; u++) {
                    const int j = c * 4 + u;
                    const int iw = __shfl_sync(0xffffffffu, wi, j);
                    const int ib = __shfl_sync(0xffffffffu, bi, j);
                    const uint4 rw = __ldg(&g_ftw_h[(long)iw * 32 + lane]);
                    const uint4 rb = __ldg(&g_ftw_h[(long)ib * 32 + lane]);
                    sw0 = __hadd2(sw0, u32_to_h2(rw.x));
                    sw1 = __hadd2(sw1, u32_to_h2(rw.y));
                    sw2 = __hadd2(sw2, u32_to_h2(rw.z));
                    sw3 = __hadd2(sw3, u32_to_h2(rw.w));
                    sb0 = __hadd2(sb0, u32_to_h2(rb.x));
                    sb1 = __hadd2(sb1, u32_to_h2(rb.y));
                    sb2 = __hadd2(sb2, u32_to_h2(rb.z));
                    sb3 = __hadd2(sb3, u32_to_h2(rb.w));
                }
                float2 f0 = __half22float2(sw0), f1 = __half22float2(sw1);
                float2 f2 = __half22float2(sw2), f3 = __half22float2(sw3);
                w[0]+=f0.x; w[1]+=f0.y; w[2]+=f1.x; w[3]+=f1.y;
                w[4]+=f2.x; w[5]+=f2.y; w[6]+=f3.x; w[7]+=f3.y;
                f0 = __half22float2(sb0); f1 = __half22float2(sb1);
                f2 = __half22float2(sb2); f3 = __half22float2(sb3);
                b[0]+=f0.x; b[1]+=f0.y; b[2]+=f1.x; b[3]+=f1.y;
                b[4]+=f2.x; b[5]+=f2.y; b[6]+=f3.x; b[7]+=f3.y;
            }

            float4 cw0 = make_float4(satf(w[0]+fbA.x), satf(w[1]+fbA.y),
                                     satf(w[2]+fbA.z), satf(w[3]+fbA.w));
            float4 cw1 = make_float4(satf(w[4]+fbB.x), satf(w[5]+fbB.y),
                                     satf(w[6]+fbB.z), satf(w[7]+fbB.w));
            float4 cb0 = make_float4(satf(b[0]+fbA.x), satf(b[1]+fbA.y),
                                     satf(b[2]+fbA.z), satf(b[3]+fbA.w));
            float4 cb1 = make_float4(satf(b[4]+fbB.x), satf(b[5]+fbB.y),
                                     satf(b[6]+fbB.z), satf(b[7]+fbB.w));

            const float s = stm[pos];
            const bool wfirst = (s > 0.5f);
            accp[2*lane]          = wfirst ? cw0 : cb0;
            accp[2*lane + 1]      = wfirst ? cw1 : cb1;
            accp[64 + 2*lane]     = wfirst ? cb0 : cw0;
            accp[64 + 2*lane + 1] = wfirst ? cb1 : cw1;
        }
        __syncwarp();

        network_tail(sh_w1h, sh_l2t, acc0_u2, acc1_u2,
                     l1b, l2b, l3w, l3b, lane, p0, p1, out);
    }
}

extern "C" void kernel_launch(void* const* d_in, const int* in_sizes, int n_in,
                              void* d_out, int out_size)
{
    const int*   white_idx = (const int*)  d_in[0];
    const int*   black_idx = (const int*)  d_in[1];
    const float* stm       = (const float*)d_in[2];
    const float* ft_w      = (const float*)d_in[3];
    const float* ft_b      = (const float*)d_in[4];
    const float* l1_w      = (const float*)d_in[5];
    const float* l1_b      = (const float*)d_in[6];
    const float* l2_w      = (const float*)d_in[7];
    const float* l2_b      = (const float*)d_in[8];
    const float* l3_w      = (const float*)d_in[9];
    const float* l3_b      = (const float*)d_in[10];
    float* out = (float*)d_out;

    const int B = in_sizes[0] / ACTIVE;
    const int n_u4 = INPUTSZ * 32;
    prepass_kernel<<<(n_u4 + NTHREADS - 1) / NTHREADS, NTHREADS>>>(ft_w, l1_w, n_u4);

    // Build the gather4 tensor map (host-side; deterministic per environment).
    typedef CUresult (CUDAAPI *tmap_encode_fn)(
        CUtensorMap*, CUtensorMapDataType, cuuint32_t, void*,
        const cuuint64_t*, const cuuint64_t*, const cuuint32_t*, const cuuint32_t*,
        CUtensorMapInterleave, CUtensorMapSwizzle, CUtensorMapL2promotion,
        CUtensorMapFloatOOBfill);
    CUtensorMap tmap;
    memset(&tmap, 0, sizeof(tmap));
    bool tma_ok = false;
    {
        void* entry = nullptr;
        cudaDriverEntryPointQueryResult qr;
        if (cudaGetDriverEntryPoint("cuTensorMapEncodeTiled", &entry,
                                    cudaEnableDefault, &qr) == cudaSuccess &&
            entry != nullptr) {
            void* tbl = nullptr;
            if (cudaGetSymbolAddress(&tbl, g_ftw_h) == cudaSuccess) {
                cuuint64_t dims[2]    = {128, INPUTSZ};   // 128 u32 elems/row
                cuuint64_t strides[1] = {ROWB};           // 512 B row stride
                cuuint32_t box[2]     = {128, 1};
                cuuint32_t es[2]      = {1, 1};
                CUresult r = ((tmap_encode_fn)entry)(
                    &tmap, CU_TENSOR_MAP_DATA_TYPE_UINT32, 2, tbl,
                    dims, strides, box, es,
                    CU_TENSOR_MAP_INTERLEAVE_NONE, CU_TENSOR_MAP_SWIZZLE_NONE,
                    CU_TENSOR_MAP_L2_PROMOTION_L2_128B,
                    CU_TENSOR_MAP_FLOAT_OOB_FILL_NONE);
                tma_ok = (r == CUDA_SUCCESS);
            }
        }
    }

    const int grid = 296;   // 2 CTAs/SM on 148 SMs
    if (tma_ok) {
        cudaFuncSetAttribute(nnue_hybrid_kernel,
                             cudaFuncAttributeMaxDynamicSharedMemorySize,
                             (int)SMEM_BYTES);
        nnue_hybrid_kernel<<<grid, NTHREADS, SMEM_BYTES>>>(
            white_idx, black_idx, stm, ft_b, l2_w,
            l1_b, l2_b, l3_w, l3_b, out, tmap, B);
    } else {
        cudaFuncSetAttribute(nnue_fallback_kernel,
                             cudaFuncAttributeMaxDynamicSharedMemorySize,
                             (int)SMEM_BYTES);
        nnue_fallback_kernel<<<grid, NTHREADS, SMEM_BYTES>>>(
            white_idx, black_idx, stm, ft_b, l2_w,
            l1_b, l2_b, l3_w, l3_b, out, B);
    }
}

// round 15
// speedup vs baseline: 1.0850x; 1.0850x over previous
#include <cuda_runtime.h>
#include <cuda_fp16.h>

#define ACTIVE     32
#define HIDDEN     256
#define ACCDIM     512
#define NTHREADS   256
#define NWARPS     (NTHREADS / 32)
#define INPUTSZ    40960

__device__ __forceinline__ unsigned int h2_to_u32(__half2 h) {
    return *reinterpret_cast<unsigned int*>(&h);
}
__device__ __forceinline__ __half2 u32_to_h2(unsigned int u) {
    return *reinterpret_cast<__half2*>(&u);
}
__device__ __forceinline__ float satf(float x) { return __saturatef(x); }

// packed f32x2 FMA (sm_100a; ptxas never emits from C++)
__device__ __forceinline__ void fma_f32x2(unsigned long long& d,
                                          unsigned long long a,
                                          unsigned long long b) {
    asm("fma.rn.f32x2 %0, %1, %2, %0;" : "+l"(d) : "l"(a), "l"(b));
}
__device__ __forceinline__ float f32x2_hsum(unsigned long long v) {
    unsigned int lo, hi;
    asm("mov.b64 {%0,%1}, %2;" : "=r"(lo), "=r"(hi) : "l"(v));
    return __uint_as_float(lo) + __uint_as_float(hi);
}

// fp16 shadow of ft_w: 40960 rows x 256 halves = 512B/row = 32 uint4 per row.
__device__ uint4 g_ftw_h[INPUTSZ * 32];
// l1_w transposed fp32: [j4][k] -> float4 (cols 4j4..4j4+3 of output row k)
__device__ float4 g_l1w_f[128 * 32];

// dynamic smem (per CTA):
//   sh_w1f : 128*32 float4 (64 KB)  transposed fp32 L1 weights
//   sh_l2t : 32*32  float  ( 4 KB)  l2_w transposed [j][k]
//   sh_acc : NWARPS*2*512 float (32 KB)
#define SMEM_W1F     (128 * 32)
#define SMEM_L2T     (32 * 32)
#define SMEM_ACC     (NWARPS * 2 * ACCDIM)
#define SMEM_BYTES   (SMEM_W1F * 16 + (SMEM_L2T + SMEM_ACC) * 4)

// ---------- merged prepass: ONE launch, grid-stride, streaming reads ----------
#define PRE_GRID   1184    // 8 blocks/SM on 148 SMs
__global__ void prepass_kernel(const float* __restrict__ ft_w,
                               const float* __restrict__ l1_w)
{
    const int n_u4 = INPUTSZ * 32;          // one uint4 out = 8 halves = 2 float4 in
    const float4* src = (const float4*)ft_w;
    for (int i = blockIdx.x * blockDim.x + threadIdx.x; i < n_u4;
         i += PRE_GRID * NTHREADS) {
        float4 a = __ldcs(&src[2 * i]);
        float4 b = __ldcs(&src[2 * i + 1]);
        uint4 o;
        o.x = h2_to_u32(__floats2half2_rn(a.x, a.y));
        o.y = h2_to_u32(__floats2half2_rn(a.z, a.w));
        o.z = h2_to_u32(__floats2half2_rn(b.x, b.y));
        o.w = h2_to_u32(__floats2half2_rn(b.z, b.w));
        g_ftw_h[i] = o;
    }
    if (blockIdx.x == 0) {                  // l1_w transpose-pack (4096 float4)
        for (int t = threadIdx.x; t < 128 * 32; t += NTHREADS) {
            int j4 = t >> 5, k = t & 31;
            const float* r = l1_w + k * ACCDIM + j4 * 4;
            g_l1w_f[t] = make_float4(r[0], r[1], r[2], r[3]);
        }
    }
}

// ---------- main fused kernel (R6 champion body) ----------
__global__ __launch_bounds__(NTHREADS, 2)
void nnue_fused_kernel(
    const int*   __restrict__ white_idx,
    const int*   __restrict__ black_idx,
    const float* __restrict__ stm,
    const float* __restrict__ ft_b,
    const float* __restrict__ l2_w,
    const float* __restrict__ l1_b,
    const float* __restrict__ l2_b,
    const float* __restrict__ l3_w,
    const float* __restrict__ l3_b,
    float*       __restrict__ out,
    int B)
{
    extern __shared__ float sm[];
    ulonglong2* sh_w1f = (ulonglong2*)sm;                 // [128][32] float4
    float* sh_l2t = sm + SMEM_W1F * 4;                    // [32][32]
    float* sh_acc = sh_l2t + SMEM_L2T;

    const int tid = threadIdx.x;

    {
        const uint4* srcw = (const uint4*)g_l1w_f;
        uint4* dstw = (uint4*)sh_w1f;
        for (int i = tid; i < SMEM_W1F; i += NTHREADS)
            dstw[i] = srcw[i];
    }
    for (int i = tid; i < SMEM_L2T; i += NTHREADS) {
        int j = i >> 5, k = i & 31;
        sh_l2t[i] = l2_w[k * 32 + j];
    }
    __syncthreads();

    const int lane  = tid & 31;
    const int warp  = tid >> 5;
    const int gwarp = blockIdx.x * NWARPS + warp;
    const int wstride = gridDim.x * NWARPS;

    float4* acc0_4 = (float4*)(sh_acc + warp * 2 * ACCDIM);   // 128 float4
    float4* acc1_4 = acc0_4 + (ACCDIM / 4);
    const ulonglong2* acc0_u2 = (const ulonglong2*)acc0_4;
    const ulonglong2* acc1_u2 = (const ulonglong2*)acc1_4;

    const float l1b = l1_b[lane];
    const float l2b = l2_b[lane];
    const float l3w = l3_w[lane];
    const float l3b = l3_b[0];
    // lane owns columns [8*lane, 8*lane+8)
    const float4* ftb4 = (const float4*)ft_b;
    const float4 fbA = ftb4[2 * lane];
    const float4 fbB = ftb4[2 * lane + 1];

    const int G = B >> 1;

    for (int g = gwarp; g < G; g += wstride) {
        const int p0 = g * 2;
        const int p1 = p0 + 1;

        // ---- feature transform + select, both positions ----
        #pragma unroll
        for (int pp = 0; pp < 2; pp++) {
            const int pos = pp ? p1 : p0;
            float4* accp = pp ? acc1_4 : acc0_4;

            const int wi = white_idx[pos * ACTIVE + lane];
            const int bi = black_idx[pos * ACTIVE + lane];

            float w0=0.f,w1=0.f,w2=0.f,w3=0.f,w4=0.f,w5=0.f,w6=0.f,w7=0.f;
            float b0=0.f,b1=0.f,b2=0.f,b3=0.f,b4=0.f,b5=0.f,b6=0.f,b7=0.f;

            const __half2 hz = u32_to_h2(0u);

            // 8 chunks of 4 indices; fp16 HADD2 within chunk, fp32 combine
            #pragma unroll
            for (int c = 0; c < 8; c++) {
                __half2 sw0=hz, sw1=hz, sw2=hz, sw3=hz;
                __half2 sb0=hz, sb1=hz, sb2=hz, sb3=hz;
                #pragma unroll
                for (int u = 0; u < 4; u++) {
                    const int j = c * 4 + u;
                    const int iw = __shfl_sync(0xffffffffu, wi, j);
                    const int ib = __shfl_sync(0xffffffffu, bi, j);
                    const uint4 rw = __ldg(&g_ftw_h[(long)iw * 32 + lane]);
                    const uint4 rb = __ldg(&g_ftw_h[(long)ib * 32 + lane]);
                    sw0 = __hadd2(sw0, u32_to_h2(rw.x));
                    sw1 = __hadd2(sw1, u32_to_h2(rw.y));
                    sw2 = __hadd2(sw2, u32_to_h2(rw.z));
                    sw3 = __hadd2(sw3, u32_to_h2(rw.w));
                    sb0 = __hadd2(sb0, u32_to_h2(rb.x));
                    sb1 = __hadd2(sb1, u32_to_h2(rb.y));
                    sb2 = __hadd2(sb2, u32_to_h2(rb.z));
                    sb3 = __hadd2(sb3, u32_to_h2(rb.w));
                }
                {
                    float2 f0 = __half22float2(sw0);
                    float2 f1 = __half22float2(sw1);
                    float2 f2 = __half22float2(sw2);
                    float2 f3 = __half22float2(sw3);
                    w0 += f0.x; w1 += f0.y; w2 += f1.x; w3 += f1.y;
                    w4 += f2.x; w5 += f2.y; w6 += f3.x; w7 += f3.y;
                }
                {
                    float2 f0 = __half22float2(sb0);
                    float2 f1 = __half22float2(sb1);
                    float2 f2 = __half22float2(sb2);
                    float2 f3 = __half22float2(sb3);
                    b0 += f0.x; b1 += f0.y; b2 += f1.x; b3 += f1.y;
                    b4 += f2.x; b5 += f2.y; b6 += f3.x; b7 += f3.y;
                }
            }

            float4 cw0 = make_float4(satf(w0+fbA.x), satf(w1+fbA.y),
                                     satf(w2+fbA.z), satf(w3+fbA.w));
            float4 cw1 = make_float4(satf(w4+fbB.x), satf(w5+fbB.y),
                                     satf(w6+fbB.z), satf(w7+fbB.w));
            float4 cb0 = make_float4(satf(b0+fbA.x), satf(b1+fbA.y),
                                     satf(b2+fbA.z), satf(b3+fbA.w));
            float4 cb1 = make_float4(satf(b4+fbB.x), satf(b5+fbB.y),
                                     satf(b6+fbB.z), satf(b7+fbB.w));

            const float s = stm[pos];
            const bool wfirst = (s > 0.5f);
            accp[2*lane]          = wfirst ? cw0 : cb0;
            accp[2*lane + 1]      = wfirst ? cw1 : cb1;
            accp[64 + 2*lane]     = wfirst ? cb0 : cw0;
            accp[64 + 2*lane + 1] = wfirst ? cb1 : cw1;
        }
        __syncwarp();

        // ---- L1: lane k computes output k for both positions (f32x2 FMA) ----
        unsigned long long q00 = 0ull, q01 = 0ull;
        unsigned long long q10 = 0ull, q11 = 0ull;
        const ulonglong2* wrow = sh_w1f + lane;
        #pragma unroll 4
        for (int j4 = 0; j4 < 128; j4++) {
            const ulonglong2 wv = wrow[j4 * 32];     // conflict-free
            const ulonglong2 a0 = acc0_u2[j4];       // broadcast
            const ulonglong2 a1 = acc1_u2[j4];       // broadcast
            fma_f32x2(q00, a0.x, wv.x);
            fma_f32x2(q01, a0.y, wv.y);
            fma_f32x2(q10, a1.x, wv.x);
            fma_f32x2(q11, a1.y, wv.y);
        }
        const float x1_0 = satf(f32x2_hsum(q00) + f32x2_hsum(q01) + l1b);
        const float x1_1 = satf(f32x2_hsum(q10) + f32x2_hsum(q11) + l1b);
        __syncwarp();   // acc reads done before next pair's stores

        // ---- L2 + L3 ----
        #pragma unroll
        for (int pp = 0; pp < 2; pp++) {
            const float x1 = pp ? x1_1 : x1_0;
            float s2 = l2b;
            #pragma unroll
            for (int j = 0; j < 32; j++) {
                const float xj = __shfl_sync(0xffffffffu, x1, j);
                s2 += xj * sh_l2t[j * 32 + lane];
            }
            const float x2 = satf(s2);
            float p = x2 * l3w;
            #pragma unroll
            for (int off = 16; off > 0; off >>= 1)
                p += __shfl_xor_sync(0xffffffffu, p, off);
            if (lane == 0)
                out[pp ? p1 : p0] = p + l3b;
        }
    }
}

extern "C" void kernel_launch(void* const* d_in, const int* in_sizes, int n_in,
                              void* d_out, int out_size)
{
    const int*   white_idx = (const int*)  d_in[0];
    const int*   black_idx = (const int*)  d_in[1];
    const float* stm       = (const float*)d_in[2];
    const float* ft_w      = (const float*)d_in[3];
    const float* ft_b      = (const float*)d_in[4];
    const float* l1_w      = (const float*)d_in[5];
    const float* l1_b      = (const float*)d_in[6];
    const float* l2_w      = (const float*)d_in[7];
    const float* l2_b      = (const float*)d_in[8];
    const float* l3_w      = (const float*)d_in[9];
    const float* l3_b      = (const float*)d_in[10];
    float* out = (float*)d_out;

    const int B = in_sizes[0] / ACTIVE;

    // single merged prepass launch (fp16 table + packed L1 weights)
    prepass_kernel<<<PRE_GRID, NTHREADS>>>(ft_w, l1_w);

    cudaFuncSetAttribute(nnue_fused_kernel,
                         cudaFuncAttributeMaxDynamicSharedMemorySize,
                         (int)SMEM_BYTES);
    const int grid = 296;   // 2 CTAs/SM on 148 SMs
    nnue_fused_kernel<<<grid, NTHREADS, SMEM_BYTES>>>(
        white_idx, black_idx, stm, ft_b, l2_w,
        l1_b, l2_b, l3_w, l3_b, out, B);
}

// round 16
// speedup vs baseline: 1.1513x; 1.0611x over previous
#include <cuda_runtime.h>
#include <cuda_fp16.h>

#define ACTIVE     32
#define HIDDEN     256
#define ACCDIM     512
#define NTHREADS   256
#define NWARPS     (NTHREADS / 32)
#define INPUTSZ    40960

__device__ __forceinline__ unsigned int h2_to_u32(__half2 h) {
    return *reinterpret_cast<unsigned int*>(&h);
}
__device__ __forceinline__ __half2 u32_to_h2(unsigned int u) {
    return *reinterpret_cast<__half2*>(&u);
}
__device__ __forceinline__ float satf(float x) { return __saturatef(x); }

// packed f32x2 FMA (sm_100a; ptxas never emits from C++)
__device__ __forceinline__ void fma_f32x2(unsigned long long& d,
                                          unsigned long long a,
                                          unsigned long long b) {
    asm("fma.rn.f32x2 %0, %1, %2, %0;" : "+l"(d) : "l"(a), "l"(b));
}
__device__ __forceinline__ float f32x2_hsum(unsigned long long v) {
    unsigned int lo, hi;
    asm("mov.b64 {%0,%1}, %2;" : "=r"(lo), "=r"(hi) : "l"(v));
    return __uint_as_float(lo) + __uint_as_float(hi);
}

// fp16 shadow of ft_w: 40960 rows x 256 halves = 512B/row = 32 uint4 per row.
__device__ uint4 g_ftw_h[INPUTSZ * 32];
// l1_w transposed fp32: [j4][k] -> float4 (cols 4j4..4j4+3 of output row k)
__device__ float4 g_l1w_f[128 * 32];

// dynamic smem (per CTA):
//   sh_w1f : 128*32 float4 (64 KB)  transposed fp32 L1 weights
//   sh_l2t : 32*32  float  ( 4 KB)  l2_w transposed [j][k]
//   sh_acc : NWARPS*2*512 float (32 KB)
#define SMEM_W1F     (128 * 32)
#define SMEM_L2T     (32 * 32)
#define SMEM_ACC     (NWARPS * 2 * ACCDIM)
#define SMEM_BYTES   (SMEM_W1F * 16 + (SMEM_L2T + SMEM_ACC) * 4)

// ---------- prepass: ONE launch, partitioned by block (no straggler) ----------
// blocks [0, 5120)    : table convert, one uint4 per thread (R6 shape)
// blocks [5120, 5136) : l1_w transpose-pack, one float4 per thread
#define CONV_BLOCKS  (INPUTSZ * 32 / NTHREADS)   // 5120
#define PACK_BLOCKS  (128 * 32 / NTHREADS)       // 16
__global__ void prepass_kernel(const float* __restrict__ ft_w,
                               const float* __restrict__ l1_w)
{
    if (blockIdx.x < CONV_BLOCKS) {
        const int i = blockIdx.x * NTHREADS + threadIdx.x;   // uint4 index
        const float4* src = (const float4*)ft_w;
        float4 a = __ldcs(&src[2 * i]);
        float4 b = __ldcs(&src[2 * i + 1]);
        uint4 o;
        o.x = h2_to_u32(__floats2half2_rn(a.x, a.y));
        o.y = h2_to_u32(__floats2half2_rn(a.z, a.w));
        o.z = h2_to_u32(__floats2half2_rn(b.x, b.y));
        o.w = h2_to_u32(__floats2half2_rn(b.z, b.w));
        g_ftw_h[i] = o;
    } else {
        const int t = (blockIdx.x - CONV_BLOCKS) * NTHREADS + threadIdx.x;
        const int j4 = t >> 5, k = t & 31;
        const float* r = l1_w + k * ACCDIM + j4 * 4;
        g_l1w_f[t] = make_float4(r[0], r[1], r[2], r[3]);
    }
}

// ---------- main fused kernel (R6 champion body, unchanged) ----------
__global__ __launch_bounds__(NTHREADS, 2)
void nnue_fused_kernel(
    const int*   __restrict__ white_idx,
    const int*   __restrict__ black_idx,
    const float* __restrict__ stm,
    const float* __restrict__ ft_b,
    const float* __restrict__ l2_w,
    const float* __restrict__ l1_b,
    const float* __restrict__ l2_b,
    const float* __restrict__ l3_w,
    const float* __restrict__ l3_b,
    float*       __restrict__ out,
    int B)
{
    extern __shared__ float sm[];
    ulonglong2* sh_w1f = (ulonglong2*)sm;                 // [128][32] float4
    float* sh_l2t = sm + SMEM_W1F * 4;                    // [32][32]
    float* sh_acc = sh_l2t + SMEM_L2T;

    const int tid = threadIdx.x;

    {
        const uint4* srcw = (const uint4*)g_l1w_f;
        uint4* dstw = (uint4*)sh_w1f;
        for (int i = tid; i < SMEM_W1F; i += NTHREADS)
            dstw[i] = srcw[i];
    }
    for (int i = tid; i < SMEM_L2T; i += NTHREADS) {
        int j = i >> 5, k = i & 31;
        sh_l2t[i] = l2_w[k * 32 + j];
    }
    __syncthreads();

    const int lane  = tid & 31;
    const int warp  = tid >> 5;
    const int gwarp = blockIdx.x * NWARPS + warp;
    const int wstride = gridDim.x * NWARPS;

    float4* acc0_4 = (float4*)(sh_acc + warp * 2 * ACCDIM);   // 128 float4
    float4* acc1_4 = acc0_4 + (ACCDIM / 4);
    const ulonglong2* acc0_u2 = (const ulonglong2*)acc0_4;
    const ulonglong2* acc1_u2 = (const ulonglong2*)acc1_4;

    const float l1b = l1_b[lane];
    const float l2b = l2_b[lane];
    const float l3w = l3_w[lane];
    const float l3b = l3_b[0];
    // lane owns columns [8*lane, 8*lane+8)
    const float4* ftb4 = (const float4*)ft_b;
    const float4 fbA = ftb4[2 * lane];
    const float4 fbB = ftb4[2 * lane + 1];

    const int G = B >> 1;

    for (int g = gwarp; g < G; g += wstride) {
        const int p0 = g * 2;
        const int p1 = p0 + 1;

        // ---- feature transform + select, both positions ----
        #pragma unroll
        for (int pp = 0; pp < 2; pp++) {
            const int pos = pp ? p1 : p0;
            float4* accp = pp ? acc1_4 : acc0_4;

            const int wi = white_idx[pos * ACTIVE + lane];
            const int bi = black_idx[pos * ACTIVE + lane];

            float w0=0.f,w1=0.f,w2=0.f,w3=0.f,w4=0.f,w5=0.f,w6=0.f,w7=0.f;
            float b0=0.f,b1=0.f,b2=0.f,b3=0.f,b4=0.f,b5=0.f,b6=0.f,b7=0.f;

            const __half2 hz = u32_to_h2(0u);

            // 8 chunks of 4 indices; fp16 HADD2 within chunk, fp32 combine
            #pragma unroll
            for (int c = 0; c < 8; c++) {
                __half2 sw0=hz, sw1=hz, sw2=hz, sw3=hz;
                __half2 sb0=hz, sb1=hz, sb2=hz, sb3=hz;
                #pragma unroll
                for (int u = 0; u < 4; u++) {
                    const int j = c * 4 + u;
                    const int iw = __shfl_sync(0xffffffffu, wi, j);
                    const int ib = __shfl_sync(0xffffffffu, bi, j);
                    const uint4 rw = __ldg(&g_ftw_h[(long)iw * 32 + lane]);
                    const uint4 rb = __ldg(&g_ftw_h[(long)ib * 32 + lane]);
                    sw0 = __hadd2(sw0, u32_to_h2(rw.x));
                    sw1 = __hadd2(sw1, u32_to_h2(rw.y));
                    sw2 = __hadd2(sw2, u32_to_h2(rw.z));
                    sw3 = __hadd2(sw3, u32_to_h2(rw.w));
                    sb0 = __hadd2(sb0, u32_to_h2(rb.x));
                    sb1 = __hadd2(sb1, u32_to_h2(rb.y));
                    sb2 = __hadd2(sb2, u32_to_h2(rb.z));
                    sb3 = __hadd2(sb3, u32_to_h2(rb.w));
                }
                {
                    float2 f0 = __half22float2(sw0);
                    float2 f1 = __half22float2(sw1);
                    float2 f2 = __half22float2(sw2);
                    float2 f3 = __half22float2(sw3);
                    w0 += f0.x; w1 += f0.y; w2 += f1.x; w3 += f1.y;
                    w4 += f2.x; w5 += f2.y; w6 += f3.x; w7 += f3.y;
                }
                {
                    float2 f0 = __half22float2(sb0);
                    float2 f1 = __half22float2(sb1);
                    float2 f2 = __half22float2(sb2);
                    float2 f3 = __half22float2(sb3);
                    b0 += f0.x; b1 += f0.y; b2 += f1.x; b3 += f1.y;
                    b4 += f2.x; b5 += f2.y; b6 += f3.x; b7 += f3.y;
                }
            }

            float4 cw0 = make_float4(satf(w0+fbA.x), satf(w1+fbA.y),
                                     satf(w2+fbA.z), satf(w3+fbA.w));
            float4 cw1 = make_float4(satf(w4+fbB.x), satf(w5+fbB.y),
                                     satf(w6+fbB.z), satf(w7+fbB.w));
            float4 cb0 = make_float4(satf(b0+fbA.x), satf(b1+fbA.y),
                                     satf(b2+fbA.z), satf(b3+fbA.w));
            float4 cb1 = make_float4(satf(b4+fbB.x), satf(b5+fbB.y),
                                     satf(b6+fbB.z), satf(b7+fbB.w));

            const float s = stm[pos];
            const bool wfirst = (s > 0.5f);
            accp[2*lane]          = wfirst ? cw0 : cb0;
            accp[2*lane + 1]      = wfirst ? cw1 : cb1;
            accp[64 + 2*lane]     = wfirst ? cb0 : cw0;
            accp[64 + 2*lane + 1] = wfirst ? cb1 : cw1;
        }
        __syncwarp();

        // ---- L1: lane k computes output k for both positions (f32x2 FMA) ----
        unsigned long long q00 = 0ull, q01 = 0ull;
        unsigned long long q10 = 0ull, q11 = 0ull;
        const ulonglong2* wrow = sh_w1f + lane;
        #pragma unroll 4
        for (int j4 = 0; j4 < 128; j4++) {
            const ulonglong2 wv = wrow[j4 * 32];     // conflict-free
            const ulonglong2 a0 = acc0_u2[j4];       // broadcast
            const ulonglong2 a1 = acc1_u2[j4];       // broadcast
            fma_f32x2(q00, a0.x, wv.x);
            fma_f32x2(q01, a0.y, wv.y);
            fma_f32x2(q10, a1.x, wv.x);
            fma_f32x2(q11, a1.y, wv.y);
        }
        const float x1_0 = satf(f32x2_hsum(q00) + f32x2_hsum(q01) + l1b);
        const float x1_1 = satf(f32x2_hsum(q10) + f32x2_hsum(q11) + l1b);
        __syncwarp();   // acc reads done before next pair's stores

        // ---- L2 + L3 ----
        #pragma unroll
        for (int pp = 0; pp < 2; pp++) {
            const float x1 = pp ? x1_1 : x1_0;
            float s2 = l2b;
            #pragma unroll
            for (int j = 0; j < 32; j++) {
                const float xj = __shfl_sync(0xffffffffu, x1, j);
                s2 += xj * sh_l2t[j * 32 + lane];
            }
            const float x2 = satf(s2);
            float p = x2 * l3w;
            #pragma unroll
            for (int off = 16; off > 0; off >>= 1)
                p += __shfl_xor_sync(0xffffffffu, p, off);
            if (lane == 0)
                out[pp ? p1 : p0] = p + l3b;
        }
    }
}

extern "C" void kernel_launch(void* const* d_in, const int* in_sizes, int n_in,
                              void* d_out, int out_size)
{
    const int*   white_idx = (const int*)  d_in[0];
    const int*   black_idx = (const int*)  d_in[1];
    const float* stm       = (const float*)d_in[2];
    const float* ft_w      = (const float*)d_in[3];
    const float* ft_b      = (const float*)d_in[4];
    const float* l1_w      = (const float*)d_in[5];
    const float* l1_b      = (const float*)d_in[6];
    const float* l2_w      = (const float*)d_in[7];
    const float* l2_b      = (const float*)d_in[8];
    const float* l3_w      = (const float*)d_in[9];
    const float* l3_b      = (const float*)d_in[10];
    float* out = (float*)d_out;

    const int B = in_sizes[0] / ACTIVE;

    // single prepass launch, partitioned by block (no serial straggler)
    prepass_kernel<<<CONV_BLOCKS + PACK_BLOCKS, NTHREADS>>>(ft_w, l1_w);

    cudaFuncSetAttribute(nnue_fused_kernel,
                         cudaFuncAttributeMaxDynamicSharedMemorySize,
                         (int)SMEM_BYTES);
    const int grid = 296;   // 2 CTAs/SM on 148 SMs
    nnue_fused_kernel<<<grid, NTHREADS, SMEM_BYTES>>>(
        white_idx, black_idx, stm, ft_b, l2_w,
        l1_b, l2_b, l3_w, l3_b, out, B);
}